// round 16
// baseline (speedup 1.0000x reference)
#include <cuda_runtime.h>
#include <cuda_bf16.h>
#include <math.h>
#include <stdint.h>

#define N_ROWS 8192
#define DIM    512
#define BM     256                  // A rows per CTA tile
#define BN     128                  // B rows per CTA tile
#define BK     64                   // bf16 -> 128 bytes per row-chunk
#define NCHUNK (DIM / BK)           // 8
#define STAGES 3
#define A_BYTES (BM * 128)          // 32768
#define B_BYTES (BN * 128)          // 16384
#define STAGE_BYTES (A_BYTES + B_BYTES)     // 49152
#define SMEM_TOTAL (STAGES * STAGE_BYTES)   // 147456
#define NTA (N_ROWS / BM)           // 32 A-tiles
#define NTB (N_ROWS / BN)           // 64 B-tiles
// valid tiles: nj >= 2*mi  ->  sum_{mi=0}^{31} (64 - 2*mi) = 1056
#define NPAIRS 1056
#define TOTAL_BLOCKS (2 * NPAIRS)   // 2112

// Normalized bf16 embeddings, row-major. [0]=txt, [1]=img halves.
__device__ __align__(16) __nv_bfloat16 g_bf[2 * N_ROWS * DIM];   // 16 MB
__device__ double g_acc[3];        // [0]=align_sum  [1]=unif_txt  [2]=unif_img
__device__ unsigned int g_done;    // finished-block counter

// ---------------------------------------------------------------- PTX helpers
__device__ __forceinline__ uint32_t smem_u32(const void* p) {
    uint32_t a;
    asm("{ .reg .u64 t; cvta.to.shared.u64 t, %1; cvt.u32.u64 %0, t; }" : "=r"(a) : "l"(p));
    return a;
}

#define CP_ASYNC16(dst, src) \
    asm volatile("cp.async.cg.shared.global [%0], [%1], 16;" :: "r"(dst), "l"(src))
#define CP_COMMIT()  asm volatile("cp.async.commit_group;" ::: "memory")
#define CP_WAIT(n)   asm volatile("cp.async.wait_group %0;" :: "n"(n) : "memory")

#define LDSM_X4(r0, r1, r2, r3, addr) \
    asm volatile("ldmatrix.sync.aligned.m8n8.x4.shared.b16 {%0,%1,%2,%3}, [%4];" \
                 : "=r"(r0), "=r"(r1), "=r"(r2), "=r"(r3) : "r"(addr))

#define MMA16816(d, a, b0, b1) \
    asm volatile("mma.sync.aligned.m16n8k16.row.col.f32.bf16.bf16.f32 " \
                 "{%0,%1,%2,%3}, {%4,%5,%6,%7}, {%8,%9}, {%0,%1,%2,%3};" \
                 : "+f"((d)[0]), "+f"((d)[1]), "+f"((d)[2]), "+f"((d)[3]) \
                 : "r"((a)[0]), "r"((a)[1]), "r"((a)[2]), "r"((a)[3]), \
                   "r"(b0), "r"(b1))

// ---------------------------------------------------------------------------
// Normalize: 2 rows per warp -> 4 independent load streams, pass 2 reloads
// (L1-hit), scales, converts to bf16, stores. 256 thr = 16 rows per block.
__global__ void __launch_bounds__(256) normalize_kernel(const float* __restrict__ img,
                                                        const float* __restrict__ txt) {
    const int w    = threadIdx.x >> 5;
    const int lane = threadIdx.x & 31;
    const int row0 = blockIdx.x * 16 + w * 2;

    const float4* i0 = reinterpret_cast<const float4*>(img + (size_t)row0 * DIM);
    const float4* i1 = reinterpret_cast<const float4*>(img + (size_t)(row0 + 1) * DIM);
    const float4* t0 = reinterpret_cast<const float4*>(txt + (size_t)row0 * DIM);
    const float4* t1 = reinterpret_cast<const float4*>(txt + (size_t)(row0 + 1) * DIM);

    float si0 = 0.f, si1 = 0.f, st0 = 0.f, st1 = 0.f;
    #pragma unroll
    for (int k = 0; k < 4; k++) {
        float4 a = i0[lane + 32 * k];
        float4 b = i1[lane + 32 * k];
        float4 c = t0[lane + 32 * k];
        float4 d = t1[lane + 32 * k];
        si0 += a.x*a.x + a.y*a.y + a.z*a.z + a.w*a.w;
        si1 += b.x*b.x + b.y*b.y + b.z*b.z + b.w*b.w;
        st0 += c.x*c.x + c.y*c.y + c.z*c.z + c.w*c.w;
        st1 += d.x*d.x + d.y*d.y + d.z*d.z + d.w*d.w;
    }
    #pragma unroll
    for (int o = 16; o; o >>= 1) {
        si0 += __shfl_xor_sync(0xffffffffu, si0, o);
        si1 += __shfl_xor_sync(0xffffffffu, si1, o);
        st0 += __shfl_xor_sync(0xffffffffu, st0, o);
        st1 += __shfl_xor_sync(0xffffffffu, st1, o);
    }
    const float ri0 = 1.0f / fmaxf(sqrtf(si0), 1e-12f);
    const float ri1 = 1.0f / fmaxf(sqrtf(si1), 1e-12f);
    const float rt0 = 1.0f / fmaxf(sqrtf(st0), 1e-12f);
    const float rt1 = 1.0f / fmaxf(sqrtf(st1), 1e-12f);

    uint2* dt0 = reinterpret_cast<uint2*>(g_bf + (size_t)row0 * DIM);
    uint2* dt1 = reinterpret_cast<uint2*>(g_bf + (size_t)(row0 + 1) * DIM);
    uint2* di0 = reinterpret_cast<uint2*>(g_bf + (size_t)N_ROWS * DIM + (size_t)row0 * DIM);
    uint2* di1 = reinterpret_cast<uint2*>(g_bf + (size_t)N_ROWS * DIM + (size_t)(row0 + 1) * DIM);

    float al = 0.0f;
    #pragma unroll
    for (int k = 0; k < 4; k++) {
        float4 a = i0[lane + 32 * k];    // L1 hits
        float4 b = i1[lane + 32 * k];
        float4 c = t0[lane + 32 * k];
        float4 d = t1[lane + 32 * k];
        float4 na = make_float4(a.x*ri0, a.y*ri0, a.z*ri0, a.w*ri0);
        float4 nb = make_float4(b.x*ri1, b.y*ri1, b.z*ri1, b.w*ri1);
        float4 nc = make_float4(c.x*rt0, c.y*rt0, c.z*rt0, c.w*rt0);
        float4 nd = make_float4(d.x*rt1, d.y*rt1, d.z*rt1, d.w*rt1);

        float dx = na.x-nc.x, dy = na.y-nc.y, dz = na.z-nc.z, dw = na.w-nc.w;
        al += dx*dx + dy*dy + dz*dz + dw*dw;
        dx = nb.x-nd.x; dy = nb.y-nd.y; dz = nb.z-nd.z; dw = nb.w-nd.w;
        al += dx*dx + dy*dy + dz*dz + dw*dw;

        uint2 v;
        v.x = (uint32_t)__bfloat16_as_ushort(__float2bfloat16_rn(nc.x)) |
              ((uint32_t)__bfloat16_as_ushort(__float2bfloat16_rn(nc.y)) << 16);
        v.y = (uint32_t)__bfloat16_as_ushort(__float2bfloat16_rn(nc.z)) |
              ((uint32_t)__bfloat16_as_ushort(__float2bfloat16_rn(nc.w)) << 16);
        dt0[lane + 32 * k] = v;
        v.x = (uint32_t)__bfloat16_as_ushort(__float2bfloat16_rn(nd.x)) |
              ((uint32_t)__bfloat16_as_ushort(__float2bfloat16_rn(nd.y)) << 16);
        v.y = (uint32_t)__bfloat16_as_ushort(__float2bfloat16_rn(nd.z)) |
              ((uint32_t)__bfloat16_as_ushort(__float2bfloat16_rn(nd.w)) << 16);
        dt1[lane + 32 * k] = v;
        v.x = (uint32_t)__bfloat16_as_ushort(__float2bfloat16_rn(na.x)) |
              ((uint32_t)__bfloat16_as_ushort(__float2bfloat16_rn(na.y)) << 16);
        v.y = (uint32_t)__bfloat16_as_ushort(__float2bfloat16_rn(na.z)) |
              ((uint32_t)__bfloat16_as_ushort(__float2bfloat16_rn(na.w)) << 16);
        di0[lane + 32 * k] = v;
        v.x = (uint32_t)__bfloat16_as_ushort(__float2bfloat16_rn(nb.x)) |
              ((uint32_t)__bfloat16_as_ushort(__float2bfloat16_rn(nb.y)) << 16);
        v.y = (uint32_t)__bfloat16_as_ushort(__float2bfloat16_rn(nb.z)) |
              ((uint32_t)__bfloat16_as_ushort(__float2bfloat16_rn(nb.w)) << 16);
        di1[lane + 32 * k] = v;
    }
    #pragma unroll
    for (int o = 16; o; o >>= 1) al += __shfl_xor_sync(0xffffffffu, al, o);
    if (lane == 0)
        atomicAdd(&g_acc[0], (double)al);
}

// ---------------------------------------------------------------------------
// 256x128 Gram tile, 512 threads (16 warps, warp tile m64 x n32), 1 CTA/SM,
// 3-stage cp.async pipeline, one sync per chunk, fused exp epilogue.
// Valid tiles: nj >= 2*mi. Fast weight-2 path when nj >= 2*mi + 2.
// Last finishing block computes the final scalar (float-only) and resets.
__global__ void __launch_bounds__(512, 1) gram_mma_kernel(float* __restrict__ out) {
    // decode flat pair index -> (mi, nj) with nj >= 2*mi
    int idx = blockIdx.x;
    int mi = 0;
    while (idx >= NTB - 2 * mi) { idx -= NTB - 2 * mi; mi++; }
    const int nj = 2 * mi + idx;
    const int z  = blockIdx.y;

    extern __shared__ char smem[];
    const uint32_t sb = smem_u32(smem);
    const int t = threadIdx.x, lane = t & 31, wid = t >> 5;
    const int wm = (wid & 3) * 64;       // 4 x 4 warp grid
    const int wn = (wid >> 2) * 32;

    const unsigned char* Pb =
        reinterpret_cast<const unsigned char*>(g_bf) + (size_t)z * N_ROWS * DIM * 2;

    float acc[4][4][4];
    #pragma unroll
    for (int f = 0; f < 4; f++)
        #pragma unroll
        for (int p = 0; p < 4; p++)
            #pragma unroll
            for (int e = 0; e < 4; e++) acc[f][p][e] = 0.0f;

    const size_t a_row0 = (size_t)mi * BM;
    const size_t b_row0 = (size_t)nj * BN;

    // stage load: (256 + 128) rows x 128B = 3072 x 16B chunks, 512 thr x 6
    #define LOAD_STAGE(s, c) do {                                              \
        uint32_t dst0 = sb + (uint32_t)(s) * STAGE_BYTES;                      \
        _Pragma("unroll")                                                      \
        for (int i_ = 0; i_ < 6; i_++) {                                       \
            int idx2 = t + i_ * 512;            /* 0..3071 */                  \
            int isB  = idx2 >= 2048;                                           \
            int r    = isB ? ((idx2 - 2048) >> 3) : (idx2 >> 3);               \
            int cb   = (idx2 & 7) * 16;                                        \
            size_t grow = (isB ? b_row0 : a_row0) + (size_t)r;                 \
            const unsigned char* src = Pb + grow * (DIM * 2) + (c) * 128 + cb; \
            uint32_t dst = dst0 + (isB ? (uint32_t)A_BYTES : 0u)               \
                           + (uint32_t)r * 128                                 \
                           + (uint32_t)(cb ^ ((r & 7) << 4));                  \
            CP_ASYNC16(dst, src);                                              \
        }                                                                      \
        CP_COMMIT();                                                           \
    } while (0)

    LOAD_STAGE(0, 0);
    LOAD_STAGE(1, 1);

    #pragma unroll 1
    for (int c = 0; c < NCHUNK; c++) {
        const int s = c % STAGES;
        if (c + STAGES - 1 < NCHUNK) CP_WAIT(1); else CP_WAIT(0);
        __syncthreads();
        if (c + STAGES - 1 < NCHUNK) LOAD_STAGE((c + STAGES - 1) % STAGES, c + STAGES - 1);

        const uint32_t abase = sb + (uint32_t)s * STAGE_BYTES;
        const uint32_t bbase = abase + A_BYTES;

        #pragma unroll
        for (int ks = 0; ks < 4; ks++) {          // 4 x k16 within BK=64
            uint32_t a[4][4], b[2][4];
            #pragma unroll
            for (int f = 0; f < 4; f++) {
                int row = wm + f * 16 + (lane & 15);
                uint32_t bo = (uint32_t)((ks * 32 + ((lane >> 4) << 4)) ^ ((row & 7) << 4));
                LDSM_X4(a[f][0], a[f][1], a[f][2], a[f][3], abase + (uint32_t)row * 128 + bo);
            }
            #pragma unroll
            for (int p = 0; p < 2; p++) {
                int rowB = wn + p * 16 + (lane & 7) + (((lane >> 4) & 1) << 3);
                uint32_t bo = (uint32_t)((ks * 32 + (((lane >> 3) & 1) << 4)) ^ ((rowB & 7) << 4));
                LDSM_X4(b[p][0], b[p][1], b[p][2], b[p][3], bbase + (uint32_t)rowB * 128 + bo);
            }
            #pragma unroll
            for (int f = 0; f < 4; f++) {
                MMA16816(acc[f][0], a[f], b[0][0], b[0][1]);   // n  0- 7
                MMA16816(acc[f][1], a[f], b[0][2], b[0][3]);   // n  8-15
                MMA16816(acc[f][2], a[f], b[1][0], b[1][1]);   // n 16-23
                MMA16816(acc[f][3], a[f], b[1][2], b[1][3]);   // n 24-31
            }
        }
        // no tail sync: next iteration's top sync orders stage reuse.
    }

    // ------ fused epilogue: exp(min(4c-4,0)) ------
    float s = 0.0f;
    if (nj >= 2 * mi + 2) {
        // strictly above diagonal: every element weight 2
        #pragma unroll
        for (int f = 0; f < 4; f++)
            #pragma unroll
            for (int p = 0; p < 4; p++)
                #pragma unroll
                for (int e = 0; e < 4; e++)
                    s += __expf(fminf(4.0f * acc[f][p][e] - 4.0f, 0.0f));
        s *= 2.0f;
    } else {
        // diagonal-crossing tile: global per-element weights
        const int i_base = mi * BM + wm + (lane >> 2);
        const int j_base = nj * BN + wn + (lane & 3) * 2;
        #pragma unroll
        for (int f = 0; f < 4; f++) {
            #pragma unroll
            for (int p = 0; p < 4; p++) {
                const int j0 = j_base + p * 8;
                #pragma unroll
                for (int e = 0; e < 4; e++) {
                    const int i = i_base + f * 16 + (e >> 1) * 8;
                    const int j = j0 + (e & 1);
                    float v = __expf(fminf(4.0f * acc[f][p][e] - 4.0f, 0.0f));
                    float w = (j > i) ? 2.0f : ((j == i) ? 1.0f : 0.0f);
                    s = fmaf(w, v, s);
                }
            }
        }
    }
    #pragma unroll
    for (int o = 16; o; o >>= 1) s += __shfl_xor_sync(0xffffffffu, s, o);
    __shared__ float red[16];
    if (lane == 0) red[wid] = s;
    __syncthreads();
    if (t == 0) {
        float bs = 0.0f;
        #pragma unroll
        for (int r = 0; r < 16; r++) bs += red[r];
        atomicAdd(&g_acc[1 + z], (double)bs);

        // ---- last-block finalize, float-only math (cold path) ----
        __threadfence();
        unsigned int v = atomicAdd(&g_done, 1u);
        if (v == TOTAL_BLOCKS - 1) {
            const float inv_n  = 1.0f / 8192.0f;
            const float inv_n2 = 1.0f / 67108864.0f;   // 1/8192^2
            float align = (float)g_acc[0] * inv_n;
            float ut = __logf((float)g_acc[1] * inv_n2);
            float ui = __logf((float)g_acc[2] * inv_n2);
            out[0] = 3.0f * align + 0.5f * (ut + ui);
            g_acc[0] = 0.0; g_acc[1] = 0.0; g_acc[2] = 0.0;
            __threadfence();
            g_done = 0u;
        }
    }
}

// ---------------------------------------------------------------------------
extern "C" void kernel_launch(void* const* d_in, const int* in_sizes, int n_in,
                              void* d_out, int out_size) {
    const float* img = (const float*)d_in[0];   // image_embed
    const float* txt = (const float*)d_in[1];   // text_embed
    float* out = (float*)d_out;

    cudaFuncSetAttribute(gram_mma_kernel,
                         cudaFuncAttributeMaxDynamicSharedMemorySize, SMEM_TOTAL);

    normalize_kernel<<<N_ROWS / 16, 256>>>(img, txt);
    dim3 grid(NPAIRS, 2);                       // (1056, 2) valid tiles only
    gram_mma_kernel<<<grid, 512, SMEM_TOTAL>>>(out);
}

// round 17
// speedup vs baseline: 1.1665x; 1.1665x over previous
#include <cuda_runtime.h>
#include <cuda_bf16.h>
#include <math.h>
#include <stdint.h>

#define N_ROWS 8192
#define DIM    512
#define BM     128
#define BN     128
#define BK     64                   // bf16 -> 128 bytes per row-chunk
#define NCHUNK (DIM / BK)           // 8
#define STAGES 3
#define A_BYTES (BM * 128)          // 16384
#define STAGE_BYTES (2 * A_BYTES)   // 32768
#define SMEM_TOTAL (STAGES * STAGE_BYTES)  // 98304
#define NTILE (N_ROWS / BM)         // 64 tiles per side
#define NPAIRS (NTILE * (NTILE + 1) / 2)   // 2080 upper-triangle tiles
#define TOTAL_BLOCKS (2 * NPAIRS)   // 4160

// Normalized bf16 embeddings, row-major. [0]=txt, [1]=img halves.
__device__ __align__(16) __nv_bfloat16 g_bf[2 * N_ROWS * DIM];   // 16 MB
__device__ double g_acc[3];        // [0]=align_sum  [1]=unif_txt  [2]=unif_img
__device__ unsigned int g_done;    // finished-block counter

// ---------------------------------------------------------------- PTX helpers
__device__ __forceinline__ uint32_t smem_u32(const void* p) {
    uint32_t a;
    asm("{ .reg .u64 t; cvta.to.shared.u64 t, %1; cvt.u32.u64 %0, t; }" : "=r"(a) : "l"(p));
    return a;
}

#define CP_ASYNC16(dst, src) \
    asm volatile("cp.async.cg.shared.global [%0], [%1], 16;" :: "r"(dst), "l"(src))
#define CP_COMMIT()  asm volatile("cp.async.commit_group;" ::: "memory")
#define CP_WAIT(n)   asm volatile("cp.async.wait_group %0;" :: "n"(n) : "memory")

#define LDSM_X4(r0, r1, r2, r3, addr) \
    asm volatile("ldmatrix.sync.aligned.m8n8.x4.shared.b16 {%0,%1,%2,%3}, [%4];" \
                 : "=r"(r0), "=r"(r1), "=r"(r2), "=r"(r3) : "r"(addr))

#define MMA16816(d, a, b0, b1) \
    asm volatile("mma.sync.aligned.m16n8k16.row.col.f32.bf16.bf16.f32 " \
                 "{%0,%1,%2,%3}, {%4,%5,%6,%7}, {%8,%9}, {%0,%1,%2,%3};" \
                 : "+f"((d)[0]), "+f"((d)[1]), "+f"((d)[2]), "+f"((d)[3]) \
                 : "r"((a)[0]), "r"((a)[1]), "r"((a)[2]), "r"((a)[3]), \
                   "r"(b0), "r"(b1))

// ---------------------------------------------------------------------------
// Normalize: 2 rows per warp -> 4 independent load streams, pass 2 reloads
// (L1-hit), scales, converts to bf16, stores. 256 thr = 16 rows per block.
__global__ void __launch_bounds__(256) normalize_kernel(const float* __restrict__ img,
                                                        const float* __restrict__ txt) {
    const int w    = threadIdx.x >> 5;
    const int lane = threadIdx.x & 31;
    const int row0 = blockIdx.x * 16 + w * 2;

    const float4* i0 = reinterpret_cast<const float4*>(img + (size_t)row0 * DIM);
    const float4* i1 = reinterpret_cast<const float4*>(img + (size_t)(row0 + 1) * DIM);
    const float4* t0 = reinterpret_cast<const float4*>(txt + (size_t)row0 * DIM);
    const float4* t1 = reinterpret_cast<const float4*>(txt + (size_t)(row0 + 1) * DIM);

    float si0 = 0.f, si1 = 0.f, st0 = 0.f, st1 = 0.f;
    #pragma unroll
    for (int k = 0; k < 4; k++) {
        float4 a = i0[lane + 32 * k];
        float4 b = i1[lane + 32 * k];
        float4 c = t0[lane + 32 * k];
        float4 d = t1[lane + 32 * k];
        si0 += a.x*a.x + a.y*a.y + a.z*a.z + a.w*a.w;
        si1 += b.x*b.x + b.y*b.y + b.z*b.z + b.w*b.w;
        st0 += c.x*c.x + c.y*c.y + c.z*c.z + c.w*c.w;
        st1 += d.x*d.x + d.y*d.y + d.z*d.z + d.w*d.w;
    }
    #pragma unroll
    for (int o = 16; o; o >>= 1) {
        si0 += __shfl_xor_sync(0xffffffffu, si0, o);
        si1 += __shfl_xor_sync(0xffffffffu, si1, o);
        st0 += __shfl_xor_sync(0xffffffffu, st0, o);
        st1 += __shfl_xor_sync(0xffffffffu, st1, o);
    }
    const float ri0 = 1.0f / fmaxf(sqrtf(si0), 1e-12f);
    const float ri1 = 1.0f / fmaxf(sqrtf(si1), 1e-12f);
    const float rt0 = 1.0f / fmaxf(sqrtf(st0), 1e-12f);
    const float rt1 = 1.0f / fmaxf(sqrtf(st1), 1e-12f);

    uint2* dt0 = reinterpret_cast<uint2*>(g_bf + (size_t)row0 * DIM);
    uint2* dt1 = reinterpret_cast<uint2*>(g_bf + (size_t)(row0 + 1) * DIM);
    uint2* di0 = reinterpret_cast<uint2*>(g_bf + (size_t)N_ROWS * DIM + (size_t)row0 * DIM);
    uint2* di1 = reinterpret_cast<uint2*>(g_bf + (size_t)N_ROWS * DIM + (size_t)(row0 + 1) * DIM);

    float al = 0.0f;
    #pragma unroll
    for (int k = 0; k < 4; k++) {
        float4 a = i0[lane + 32 * k];    // L1 hits
        float4 b = i1[lane + 32 * k];
        float4 c = t0[lane + 32 * k];
        float4 d = t1[lane + 32 * k];
        float4 na = make_float4(a.x*ri0, a.y*ri0, a.z*ri0, a.w*ri0);
        float4 nb = make_float4(b.x*ri1, b.y*ri1, b.z*ri1, b.w*ri1);
        float4 nc = make_float4(c.x*rt0, c.y*rt0, c.z*rt0, c.w*rt0);
        float4 nd = make_float4(d.x*rt1, d.y*rt1, d.z*rt1, d.w*rt1);

        float dx = na.x-nc.x, dy = na.y-nc.y, dz = na.z-nc.z, dw = na.w-nc.w;
        al += dx*dx + dy*dy + dz*dz + dw*dw;
        dx = nb.x-nd.x; dy = nb.y-nd.y; dz = nb.z-nd.z; dw = nb.w-nd.w;
        al += dx*dx + dy*dy + dz*dz + dw*dw;

        uint2 v;
        v.x = (uint32_t)__bfloat16_as_ushort(__float2bfloat16_rn(nc.x)) |
              ((uint32_t)__bfloat16_as_ushort(__float2bfloat16_rn(nc.y)) << 16);
        v.y = (uint32_t)__bfloat16_as_ushort(__float2bfloat16_rn(nc.z)) |
              ((uint32_t)__bfloat16_as_ushort(__float2bfloat16_rn(nc.w)) << 16);
        dt0[lane + 32 * k] = v;
        v.x = (uint32_t)__bfloat16_as_ushort(__float2bfloat16_rn(nd.x)) |
              ((uint32_t)__bfloat16_as_ushort(__float2bfloat16_rn(nd.y)) << 16);
        v.y = (uint32_t)__bfloat16_as_ushort(__float2bfloat16_rn(nd.z)) |
              ((uint32_t)__bfloat16_as_ushort(__float2bfloat16_rn(nd.w)) << 16);
        dt1[lane + 32 * k] = v;
        v.x = (uint32_t)__bfloat16_as_ushort(__float2bfloat16_rn(na.x)) |
              ((uint32_t)__bfloat16_as_ushort(__float2bfloat16_rn(na.y)) << 16);
        v.y = (uint32_t)__bfloat16_as_ushort(__float2bfloat16_rn(na.z)) |
              ((uint32_t)__bfloat16_as_ushort(__float2bfloat16_rn(na.w)) << 16);
        di0[lane + 32 * k] = v;
        v.x = (uint32_t)__bfloat16_as_ushort(__float2bfloat16_rn(nb.x)) |
              ((uint32_t)__bfloat16_as_ushort(__float2bfloat16_rn(nb.y)) << 16);
        v.y = (uint32_t)__bfloat16_as_ushort(__float2bfloat16_rn(nb.z)) |
              ((uint32_t)__bfloat16_as_ushort(__float2bfloat16_rn(nb.w)) << 16);
        di1[lane + 32 * k] = v;
    }
    #pragma unroll
    for (int o = 16; o; o >>= 1) al += __shfl_xor_sync(0xffffffffu, al, o);
    if (lane == 0)
        atomicAdd(&g_acc[0], (double)al);
}

// ---------------------------------------------------------------------------
// 128x128 Gram tile via bf16 mma.sync, 8 warps (warp tile m64 x n32),
// 3-stage cp.async pipeline (2 CTAs/SM), one sync per chunk.
// Addressing fully hoisted: loads use one base pointer per matrix with
// constant offsets (rows step 32 == 0 mod 8, so the swizzle term is
// iteration-invariant); LDSM columns are precomputed per ks (row&7 == lane&7
// for every fragment, so the swizzle is f/p-invariant).
__global__ void __launch_bounds__(256, 2) gram_mma_kernel(float* __restrict__ out) {
    // decode flat pair index -> (mi, nj) with mi <= nj
    int idx = blockIdx.x;
    int mi = 0;
    while (idx >= NTILE - mi) { idx -= NTILE - mi; mi++; }
    const int nj = mi + idx;
    const int z  = blockIdx.y;

    extern __shared__ char smem[];
    const uint32_t sb = smem_u32(smem);
    const int t = threadIdx.x, lane = t & 31, wid = t >> 5;
    const int wm = (wid & 1) * 64;       // warp m offset (2 x 4 warp grid)
    const int wn = (wid >> 1) * 32;      // warp n offset

    const unsigned char* Pb =
        reinterpret_cast<const unsigned char*>(g_bf) + (size_t)z * N_ROWS * DIM * 2;

    float acc[4][4][4];
    #pragma unroll
    for (int f = 0; f < 4; f++)
        #pragma unroll
        for (int p = 0; p < 4; p++)
            #pragma unroll
            for (int e = 0; e < 4; e++) acc[f][p][e] = 0.0f;

    // ---- hoisted load addressing ----
    // thread t copies rows rA + 32*i (i=0..3) of A and of B, 16B column cb.
    const int rA = t >> 3;                       // 0..31
    const int cb = (t & 7) * 16;
    const uint32_t dstA0 = (uint32_t)rA * 128 + (uint32_t)(cb ^ ((rA & 7) << 4));
    const uint32_t dstB0 = (uint32_t)A_BYTES + dstA0;
    const unsigned char* srcA = Pb + ((size_t)mi * BM + rA) * (DIM * 2) + cb;
    const unsigned char* srcB = Pb + ((size_t)nj * BN + rA) * (DIM * 2) + cb;

    #define LOAD_STAGE(s, c) do {                                              \
        uint32_t da = sb + (uint32_t)(s) * STAGE_BYTES + dstA0;                \
        uint32_t db = sb + (uint32_t)(s) * STAGE_BYTES + dstB0;                \
        const unsigned char* pa = srcA + (c) * 128;                            \
        const unsigned char* pb = srcB + (c) * 128;                            \
        CP_ASYNC16(da,          pa);                                           \
        CP_ASYNC16(da + 4096u,  pa + 32768);                                   \
        CP_ASYNC16(da + 8192u,  pa + 65536);                                   \
        CP_ASYNC16(da + 12288u, pa + 98304);                                   \
        CP_ASYNC16(db,          pb);                                           \
        CP_ASYNC16(db + 4096u,  pb + 32768);                                   \
        CP_ASYNC16(db + 8192u,  pb + 65536);                                   \
        CP_ASYNC16(db + 12288u, pb + 98304);                                   \
        CP_COMMIT();                                                           \
    } while (0)

    // ---- hoisted LDSM addressing ----
    const uint32_t rowbaseA = (uint32_t)(wm + (lane & 15)) * 128;
    const uint32_t rowbaseB = (uint32_t)(wn + (lane & 7) + (((lane >> 4) & 1) << 3)) * 128;
    uint32_t colA[4], colB[4];
    #pragma unroll
    for (int ks = 0; ks < 4; ks++) {
        colA[ks] = (uint32_t)((ks * 32 + ((lane >> 4) << 4)) ^ ((lane & 7) << 4));
        colB[ks] = (uint32_t)((ks * 32 + (((lane >> 3) & 1) << 4)) ^ ((lane & 7) << 4));
    }

    LOAD_STAGE(0, 0);
    LOAD_STAGE(1, 1);

    #pragma unroll 1
    for (int c = 0; c < NCHUNK; c++) {
        const int s = c % STAGES;
        if (c + STAGES - 1 < NCHUNK) CP_WAIT(1); else CP_WAIT(0);
        __syncthreads();
        if (c + STAGES - 1 < NCHUNK) LOAD_STAGE((c + STAGES - 1) % STAGES, c + STAGES - 1);

        const uint32_t aA = sb + (uint32_t)s * STAGE_BYTES + rowbaseA;
        const uint32_t aB = sb + (uint32_t)s * STAGE_BYTES + (uint32_t)A_BYTES + rowbaseB;

        #pragma unroll
        for (int ks = 0; ks < 4; ks++) {          // 4 x k16 within BK=64
            uint32_t a[4][4], b[2][4];
            const uint32_t aks = aA + colA[ks];
            const uint32_t bks = aB + colB[ks];
            #pragma unroll
            for (int f = 0; f < 4; f++)
                LDSM_X4(a[f][0], a[f][1], a[f][2], a[f][3], aks + (uint32_t)(f * 2048));
            #pragma unroll
            for (int p = 0; p < 2; p++)
                LDSM_X4(b[p][0], b[p][1], b[p][2], b[p][3], bks + (uint32_t)(p * 2048));
            #pragma unroll
            for (int f = 0; f < 4; f++) {
                MMA16816(acc[f][0], a[f], b[0][0], b[0][1]);   // n  0- 7
                MMA16816(acc[f][1], a[f], b[0][2], b[0][3]);   // n  8-15
                MMA16816(acc[f][2], a[f], b[1][0], b[1][1]);   // n 16-23
                MMA16816(acc[f][3], a[f], b[1][2], b[1][3]);   // n 24-31
            }
        }
        // no tail sync: next iteration's top sync orders stage reuse.
    }

    // ------ fused epilogue: exp(min(4c-4,0)) ------
    float s = 0.0f;
    if (nj > mi) {
        #pragma unroll
        for (int f = 0; f < 4; f++)
            #pragma unroll
            for (int p = 0; p < 4; p++)
                #pragma unroll
                for (int e = 0; e < 4; e++)
                    s += __expf(fminf(4.0f * acc[f][p][e] - 4.0f, 0.0f));
        s *= 2.0f;
    } else {
        const int i_base = wm + (lane >> 2);
        const int j_base = wn + (lane & 3) * 2;
        #pragma unroll
        for (int f = 0; f < 4; f++) {
            #pragma unroll
            for (int p = 0; p < 4; p++) {
                const int j0 = j_base + p * 8;
                #pragma unroll
                for (int e = 0; e < 4; e++) {
                    const int i = i_base + f * 16 + (e >> 1) * 8;
                    const int j = j0 + (e & 1);
                    float v = __expf(fminf(4.0f * acc[f][p][e] - 4.0f, 0.0f));
                    float w = (j > i) ? 2.0f : ((j == i) ? 1.0f : 0.0f);
                    s = fmaf(w, v, s);
                }
            }
        }
    }
    #pragma unroll
    for (int o = 16; o; o >>= 1) s += __shfl_xor_sync(0xffffffffu, s, o);
    __shared__ float red[8];
    if (lane == 0) red[wid] = s;
    __syncthreads();
    if (t == 0) {
        float bs = red[0] + red[1] + red[2] + red[3] + red[4] + red[5] + red[6] + red[7];
        atomicAdd(&g_acc[1 + z], (double)bs);

        // ---- last-block finalize, float-only math (cold path) ----
        __threadfence();
        unsigned int v = atomicAdd(&g_done, 1u);
        if (v == TOTAL_BLOCKS - 1) {
            const float inv_n  = 1.0f / 8192.0f;
            const float inv_n2 = 1.0f / 67108864.0f;   // 1/8192^2
            float align = (float)g_acc[0] * inv_n;
            float ut = __logf((float)g_acc[1] * inv_n2);
            float ui = __logf((float)g_acc[2] * inv_n2);
            out[0] = 3.0f * align + 0.5f * (ut + ui);
            g_acc[0] = 0.0; g_acc[1] = 0.0; g_acc[2] = 0.0;
            __threadfence();
            g_done = 0u;
        }
    }
}

// ---------------------------------------------------------------------------
extern "C" void kernel_launch(void* const* d_in, const int* in_sizes, int n_in,
                              void* d_out, int out_size) {
    const float* img = (const float*)d_in[0];   // image_embed
    const float* txt = (const float*)d_in[1];   // text_embed
    float* out = (float*)d_out;

    cudaFuncSetAttribute(gram_mma_kernel,
                         cudaFuncAttributeMaxDynamicSharedMemorySize, SMEM_TOTAL);

    normalize_kernel<<<N_ROWS / 16, 256>>>(img, txt);
    dim3 grid(NPAIRS, 2);                       // (2080, 2) valid tiles only
    gram_mma_kernel<<<grid, 256, SMEM_TOTAL>>>(out);
}